// round 5
// baseline (speedup 1.0000x reference)
#include <cuda_runtime.h>
#include <cuda_bf16.h>
#include <cstdint>
#include <math.h>

#define BATCH 8
#define CHN 512
#define NPIX 4096
#define GROUPS 32
#define CPG 16

// ---------------- scratch (__device__ globals) -------------------------------
__device__ __nv_bfloat16 g_ht[(size_t)BATCH*NPIX*CHN];     // h^T  [b][i][c]
__device__ __nv_bfloat16 g_qt[(size_t)BATCH*NPIX*CHN];     // q^T  [b][i][c]
__device__ __nv_bfloat16 g_kt[(size_t)BATCH*NPIX*CHN];     // k^T  [b][j][c]
__device__ __nv_bfloat16 g_v [(size_t)BATCH*CHN*NPIX];     // v    [b][c][j]
__device__ __nv_bfloat16 g_ot[(size_t)BATCH*NPIX*CHN];     // o^T  [b][i][c]
__device__ __nv_bfloat16 g_attn[(size_t)BATCH*NPIX*NPIX];  // attn [b][i][j]
__device__ __nv_bfloat16 g_wq[CHN*CHN];
__device__ __nv_bfloat16 g_wk[CHN*CHN];
__device__ __nv_bfloat16 g_wv[CHN*CHN];
__device__ __nv_bfloat16 g_wp[CHN*CHN];

// ---------------- helpers ------------------------------------------------------
__device__ __forceinline__ uint32_t smem_u32(const void* p) {
    uint32_t a;
    asm("{ .reg .u64 t; cvta.to.shared.u64 t, %1; cvt.u32.u64 %0, t; }" : "=r"(a) : "l"(p));
    return a;
}
__device__ __forceinline__ void cpa16(uint32_t s, const void* g) {
    asm volatile("cp.async.cg.shared.global [%0], [%1], 16;" :: "r"(s), "l"(g) : "memory");
}
#define CPA_COMMIT() asm volatile("cp.async.commit_group;" ::: "memory")
#define CPA_WAIT2()  asm volatile("cp.async.wait_group 2;" ::: "memory")
#define CPA_WAIT0()  asm volatile("cp.async.wait_group 0;" ::: "memory")

__device__ __forceinline__ void ldsm4(uint32_t addr, uint32_t& r0, uint32_t& r1,
                                      uint32_t& r2, uint32_t& r3) {
    asm volatile("ldmatrix.sync.aligned.m8n8.x4.shared.b16 {%0,%1,%2,%3}, [%4];"
                 : "=r"(r0), "=r"(r1), "=r"(r2), "=r"(r3) : "r"(addr));
}

// ---------------- unified bf16 mma.sync GEMM ----------------------------------
// C[m][n] = scale * (sum_k A[m][k]*B[n][k]) + bias_m[m] + bias_n[n] (+resid, fp32)
// BM=128, BN=256, BK=64; 8 warps as 2(M) x 4(N); warp tile 64x64.
#define BM 128
#define BN 256
#define BK 64
#define NSTAGE 3
#define ABYTES (BM*128)            // 16 KB
#define BBYTES (BN*128)            // 32 KB
#define STAGE_BYTES (ABYTES + BBYTES)
#define SMEM_TOTAL (NSTAGE*STAGE_BYTES)   // 144 KB

__global__ void __launch_bounds__(256, 1)
gemm_tc(const __nv_bfloat16* __restrict__ A, size_t strideA,
        const __nv_bfloat16* __restrict__ B, size_t strideB,
        void* __restrict__ Cv, size_t strideC, int ldC,
        const float* __restrict__ bias_m,
        const float* __restrict__ bias_n,
        const float* __restrict__ resid,
        float scale, int K, int out32) {
    extern __shared__ char smem[];
    uint32_t sb = smem_u32(smem);

    int tid  = threadIdx.x;
    int wid  = tid >> 5, lane = tid & 31;
    int wm = wid >> 2;         // 2 warps on M: 64 rows each
    int wn = wid & 3;          // 4 warps on N: 64 cols each
    int m0 = blockIdx.y * BM;
    int n0 = blockIdx.x * BN;
    const __nv_bfloat16* Ab = A + (size_t)blockIdx.z*strideA + (size_t)m0*K;
    const __nv_bfloat16* Bb = B + (size_t)blockIdx.z*strideB + (size_t)n0*K;

    float acc[4][8][4];
    #pragma unroll
    for (int i = 0; i < 4; i++)
        #pragma unroll
        for (int j = 0; j < 8; j++)
            #pragma unroll
            for (int r = 0; r < 4; r++) acc[i][j][r] = 0.f;

    // ---- tile copy: A 1024 + B 2048 16B-chunks; 4 + 8 per thread ----
    auto copy_stage = [&](int s, int k0) {
        uint32_t ab  = sb + s*STAGE_BYTES;
        uint32_t bbs = ab + ABYTES;
        #pragma unroll
        for (int i = 0; i < 4; i++) {
            int q = i*256 + tid;
            int r = q >> 3, c = q & 7;
            cpa16(ab + r*128 + ((c ^ (r & 7)) << 4), Ab + (size_t)r*K + k0 + c*8);
        }
        #pragma unroll
        for (int i = 0; i < 8; i++) {
            int q = i*256 + tid;
            int r = q >> 3, c = q & 7;
            cpa16(bbs + r*128 + ((c ^ (r & 7)) << 4), Bb + (size_t)r*K + k0 + c*8);
        }
        CPA_COMMIT();
    };

    int nt = K / BK;
    copy_stage(0, 0);
    copy_stage(1, BK);

    // ldmatrix address components
    int arow = wm*64 + (lane & 15);                     // + am*16
    int akc  = lane >> 4;                               // 0/1 -> +8 k elems
    int brow = wn*64 + (lane & 7) + ((lane >> 4) << 3); // + bt*16
    int bkc  = (lane >> 3) & 1;

    for (int it = 0; it < nt; it++) {
        if (it + 2 < nt) copy_stage((it + 2) % NSTAGE, (it + 2)*BK);
        if (it + 2 < nt) { CPA_WAIT2(); } else { CPA_WAIT0(); }
        __syncthreads();

        uint32_t as = sb + (it % NSTAGE)*STAGE_BYTES;
        uint32_t bs = as + ABYTES;

        #pragma unroll
        for (int ks = 0; ks < 4; ks++) {          // 4 x k16
            int kc = ks*2;
            uint32_t af[4][4];
            #pragma unroll
            for (int am = 0; am < 4; am++) {
                int r = arow + am*16;
                uint32_t addr = as + r*128 + (((kc + akc) ^ (r & 7)) << 4);
                ldsm4(addr, af[am][0], af[am][1], af[am][2], af[am][3]);
            }
            uint32_t bf[8][2];
            #pragma unroll
            for (int bt = 0; bt < 4; bt++) {
                int r = brow + bt*16;
                uint32_t addr = bs + r*128 + (((kc + bkc) ^ (r & 7)) << 4);
                ldsm4(addr, bf[bt*2][0], bf[bt*2][1], bf[bt*2+1][0], bf[bt*2+1][1]);
            }
            #pragma unroll
            for (int am = 0; am < 4; am++)
                #pragma unroll
                for (int an = 0; an < 8; an++) {
                    float* c = acc[am][an];
                    asm volatile(
                        "mma.sync.aligned.m16n8k16.row.col.f32.bf16.bf16.f32 "
                        "{%0,%1,%2,%3}, {%4,%5,%6,%7}, {%8,%9}, {%0,%1,%2,%3};"
                        : "+f"(c[0]), "+f"(c[1]), "+f"(c[2]), "+f"(c[3])
                        : "r"(af[am][0]), "r"(af[am][1]), "r"(af[am][2]), "r"(af[am][3]),
                          "r"(bf[an][0]), "r"(bf[an][1]));
                }
        }
        __syncthreads();
    }

    // ---- epilogue: all row-major, coalesced ----
    int g = lane >> 2, t = lane & 3;
    #pragma unroll
    for (int am = 0; am < 4; am++) {
        int ml = m0 + wm*64 + am*16 + g;
        int mh = ml + 8;
        float bml = bias_m ? bias_m[ml] : 0.f;
        float bmh = bias_m ? bias_m[mh] : 0.f;
        size_t rl = (size_t)blockIdx.z*strideC + (size_t)ml*ldC;
        size_t rh = (size_t)blockIdx.z*strideC + (size_t)mh*ldC;
        #pragma unroll
        for (int an = 0; an < 8; an++) {
            int ne = n0 + wn*64 + an*8 + 2*t;
            float v0 = acc[am][an][0]*scale + bml;
            float v1 = acc[am][an][1]*scale + bml;
            float v2 = acc[am][an][2]*scale + bmh;
            float v3 = acc[am][an][3]*scale + bmh;
            if (bias_n) {
                float b0 = __ldg(bias_n + ne), b1 = __ldg(bias_n + ne + 1);
                v0 += b0; v1 += b1; v2 += b0; v3 += b1;
            }
            if (!out32) {
                __nv_bfloat16* C = (__nv_bfloat16*)Cv;
                *reinterpret_cast<__nv_bfloat162*>(C + rl + ne) =
                    __nv_bfloat162{__float2bfloat16(v0), __float2bfloat16(v1)};
                *reinterpret_cast<__nv_bfloat162*>(C + rh + ne) =
                    __nv_bfloat162{__float2bfloat16(v2), __float2bfloat16(v3)};
            } else {
                float* C = (float*)Cv;
                float2 r0 = *reinterpret_cast<const float2*>(resid + rl + ne);
                float2 r1 = *reinterpret_cast<const float2*>(resid + rh + ne);
                *reinterpret_cast<float2*>(C + rl + ne) = float2{v0 + r0.x, v1 + r0.y};
                *reinterpret_cast<float2*>(C + rh + ne) = float2{v2 + r1.x, v3 + r1.y};
            }
        }
    }
}

// ---------------- fp32 -> bf16 weight convert (all 4 weights, 1 launch) -------
#define WN (CHN*CHN)
__global__ void cvt4_kernel(const float* __restrict__ s0, const float* __restrict__ s1,
                            const float* __restrict__ s2, const float* __restrict__ s3,
                            __nv_bfloat16* __restrict__ d0, __nv_bfloat16* __restrict__ d1,
                            __nv_bfloat16* __restrict__ d2, __nv_bfloat16* __restrict__ d3) {
    int i = blockIdx.x * blockDim.x + threadIdx.x;
    int sel = i >> 18;            // WN = 2^18
    int off = i & (WN - 1);
    const float* s = sel == 0 ? s0 : sel == 1 ? s1 : sel == 2 ? s2 : s3;
    __nv_bfloat16* d = sel == 0 ? d0 : sel == 1 ? d1 : sel == 2 ? d2 : d3;
    d[off] = __float2bfloat16(s[off]);
}

// ---------------- GroupNorm -> h^T bf16 [b][i][c] -----------------------------
__global__ void gn_kernel(const float* __restrict__ x,
                          const float* __restrict__ w,
                          const float* __restrict__ b,
                          __nv_bfloat16* __restrict__ ht) {
    int batch = blockIdx.x >> 5;
    int grp   = blockIdx.x & 31;
    const float* xp = x + ((size_t)batch*CHN + (size_t)grp*CPG) * NPIX;
    const int GE = CPG * NPIX;
    int tid = threadIdx.x;

    float s = 0.f, ss = 0.f;
    for (int i = tid; i < GE; i += 256) {
        float v = xp[i];
        s += v; ss += v*v;
    }
    __shared__ float r1[256], r2[256];
    r1[tid] = s; r2[tid] = ss;
    __syncthreads();
    for (int st = 128; st > 0; st >>= 1) {
        if (tid < st) { r1[tid] += r1[tid+st]; r2[tid] += r2[tid+st]; }
        __syncthreads();
    }
    float mean = r1[0] / (float)GE;
    float var  = r2[0] / (float)GE - mean*mean;
    float rstd = rsqrtf(var + 1e-6f);

    float wl[CPG], bl[CPG];
    #pragma unroll
    for (int c = 0; c < CPG; c++) { wl[c] = w[grp*CPG+c]; bl[c] = b[grp*CPG+c]; }

    for (int n = tid; n < NPIX; n += 256) {
        union { __nv_bfloat16 v[CPG]; uint4 u[2]; } pk;
        #pragma unroll
        for (int c = 0; c < CPG; c++) {
            float xv = xp[(size_t)c*NPIX + n];
            pk.v[c] = __float2bfloat16((xv - mean) * rstd * wl[c] + bl[c]);
        }
        uint4* dst = reinterpret_cast<uint4*>(ht + ((size_t)batch*NPIX + n)*CHN + grp*CPG);
        dst[0] = pk.u[0]; dst[1] = pk.u[1];
    }
}

// ---------------- row softmax, bf16 in-place ----------------------------------
__global__ void softmax_kernel(__nv_bfloat16* __restrict__ attn) {
    __nv_bfloat16* p = attn + (size_t)blockIdx.x * NPIX;
    __shared__ float buf[NPIX];
    __shared__ float red[8];
    int tid = threadIdx.x, lane = tid & 31, wid = tid >> 5;

    float mx = -1e30f;
    for (int i = tid; i < NPIX/8; i += 256) {
        uint4 raw = reinterpret_cast<const uint4*>(p)[i];
        const __nv_bfloat162* h2 = reinterpret_cast<const __nv_bfloat162*>(&raw);
        #pragma unroll
        for (int j = 0; j < 4; j++) {
            float2 f = __bfloat1622float2(h2[j]);
            buf[i*8 + 2*j]   = f.x;
            buf[i*8 + 2*j+1] = f.y;
            mx = fmaxf(mx, fmaxf(f.x, f.y));
        }
    }
    #pragma unroll
    for (int o = 16; o > 0; o >>= 1) mx = fmaxf(mx, __shfl_xor_sync(0xffffffffu, mx, o));
    if (lane == 0) red[wid] = mx;
    __syncthreads();
    if (tid == 0) {
        float m = red[0];
        #pragma unroll
        for (int i = 1; i < 8; i++) m = fmaxf(m, red[i]);
        red[0] = m;
    }
    __syncthreads();
    mx = red[0];
    __syncthreads();

    float s = 0.f;
    for (int i = tid; i < NPIX; i += 256) {
        float e = __expf(buf[i] - mx);
        buf[i] = e;
        s += e;
    }
    #pragma unroll
    for (int o = 16; o > 0; o >>= 1) s += __shfl_xor_sync(0xffffffffu, s, o);
    if (lane == 0) red[wid] = s;
    __syncthreads();
    if (tid == 0) {
        float m = 0.f;
        #pragma unroll
        for (int i = 0; i < 8; i++) m += red[i];
        red[0] = m;
    }
    __syncthreads();
    float inv = 1.0f / red[0];

    for (int i = tid; i < NPIX/8; i += 256) {
        uint4 raw;
        __nv_bfloat162* h2 = reinterpret_cast<__nv_bfloat162*>(&raw);
        #pragma unroll
        for (int j = 0; j < 4; j++) {
            h2[j] = __nv_bfloat162{__float2bfloat16(buf[i*8+2*j]   * inv),
                                   __float2bfloat16(buf[i*8+2*j+1] * inv)};
        }
        reinterpret_cast<uint4*>(p)[i] = raw;
    }
}

// ---------------- launch -------------------------------------------------------
extern "C" void kernel_launch(void* const* d_in, const int* in_sizes, int n_in,
                              void* d_out, int out_size) {
    const float* x    = (const float*)d_in[0];
    const float* gn_w = (const float*)d_in[1];
    const float* gn_b = (const float*)d_in[2];
    const float* q_w  = (const float*)d_in[3];
    const float* q_b  = (const float*)d_in[4];
    const float* k_w  = (const float*)d_in[5];
    const float* k_b  = (const float*)d_in[6];
    const float* v_w  = (const float*)d_in[7];
    const float* v_b  = (const float*)d_in[8];
    const float* p_w  = (const float*)d_in[9];
    const float* p_b  = (const float*)d_in[10];
    float* out = (float*)d_out;

    __nv_bfloat16 *ht, *qt, *kt, *v, *ot, *attn, *wq, *wk, *wv, *wp;
    cudaGetSymbolAddress((void**)&ht, g_ht);
    cudaGetSymbolAddress((void**)&qt, g_qt);
    cudaGetSymbolAddress((void**)&kt, g_kt);
    cudaGetSymbolAddress((void**)&v,  g_v);
    cudaGetSymbolAddress((void**)&ot, g_ot);
    cudaGetSymbolAddress((void**)&attn, g_attn);
    cudaGetSymbolAddress((void**)&wq, g_wq);
    cudaGetSymbolAddress((void**)&wk, g_wk);
    cudaGetSymbolAddress((void**)&wv, g_wv);
    cudaGetSymbolAddress((void**)&wp, g_wp);

    cudaFuncSetAttribute(gemm_tc, cudaFuncAttributeMaxDynamicSharedMemorySize, SMEM_TOTAL);

    cvt4_kernel<<<4*WN/256, 256>>>(q_w, k_w, v_w, p_w, wq, wk, wv, wp);
    gn_kernel<<<BATCH*GROUPS, 256>>>(x, gn_w, gn_b, ht);

    size_t sHT = (size_t)NPIX*CHN;
    size_t sCN = (size_t)CHN*NPIX;
    size_t sNN = (size_t)NPIX*NPIX;

    // q^T[i][c] = sum_k ht[i][k] Wq[c][k] + qb[c]  (M=NPIX, N=CHN, K=CHN)
    dim3 qkgrid(CHN/BN, NPIX/BM, BATCH);
    gemm_tc<<<qkgrid, 256, SMEM_TOTAL>>>(ht, sHT, wq, 0, qt, sHT, CHN,
                                         nullptr, q_b, nullptr, 1.f, CHN, 0);
    gemm_tc<<<qkgrid, 256, SMEM_TOTAL>>>(ht, sHT, wk, 0, kt, sHT, CHN,
                                         nullptr, k_b, nullptr, 1.f, CHN, 0);
    // v[c][j] = sum_k Wv[c][k] ht[j][k] + vb[c]   (M=CHN, N=NPIX, K=CHN)
    dim3 vgrid(NPIX/BN, CHN/BM, BATCH);
    gemm_tc<<<vgrid, 256, SMEM_TOTAL>>>(wv, 0, ht, sHT, v, sCN, NPIX,
                                        v_b, nullptr, nullptr, 1.f, CHN, 0);
    // attn[i][j] = scale * sum_c q^T[i][c] k^T[j][c]  (M=N=NPIX, K=CHN)
    dim3 lgrid(NPIX/BN, NPIX/BM, BATCH);
    gemm_tc<<<lgrid, 256, SMEM_TOTAL>>>(qt, sHT, kt, sHT, attn, sNN, NPIX,
                                        nullptr, nullptr, nullptr,
                                        0.044194173824159216f, CHN, 0);

    softmax_kernel<<<BATCH*NPIX, 256>>>(attn);

    // o^T[i][c] = sum_j attn[i][j] v[c][j]  (M=NPIX, N=CHN, K=NPIX)
    dim3 ogrid(CHN/BN, NPIX/BM, BATCH);
    gemm_tc<<<ogrid, 256, SMEM_TOTAL>>>(attn, sNN, v, sCN, ot, sHT, CHN,
                                        nullptr, nullptr, nullptr, 1.f, NPIX, 0);

    // out[c][n] = sum_k Wp[c][k] o^T[n][k] + pb[c] + x  (fp32 + residual)
    dim3 pgrid(NPIX/BN, CHN/BM, BATCH);
    gemm_tc<<<pgrid, 256, SMEM_TOTAL>>>(wp, 0, ot, sHT, out, sCN, NPIX,
                                        p_b, nullptr, x, 1.f, CHN, 1);
}

// round 6
// speedup vs baseline: 1.1689x; 1.1689x over previous
#include <cuda_runtime.h>
#include <cuda_bf16.h>
#include <cstdint>
#include <math.h>

#define BATCH 8
#define CHN 512
#define NPIX 4096
#define GROUPS 32
#define CPG 16

// ---------------- scratch (__device__ globals) -------------------------------
__device__ __nv_bfloat16 g_ht[(size_t)BATCH*NPIX*CHN];     // h^T  [b][i][c]
__device__ __nv_bfloat16 g_qt[(size_t)BATCH*NPIX*CHN];     // q^T  [b][i][c]
__device__ __nv_bfloat16 g_kt[(size_t)BATCH*NPIX*CHN];     // k^T  [b][j][c]
__device__ __nv_bfloat16 g_v [(size_t)BATCH*CHN*NPIX];     // v    [b][c][j]
__device__ __nv_bfloat16 g_ot[(size_t)BATCH*NPIX*CHN];     // o^T  [b][i][c]
__device__ __nv_bfloat16 g_attn[(size_t)BATCH*NPIX*NPIX];  // attn [b][i][j]
__device__ __nv_bfloat16 g_wq[CHN*CHN];
__device__ __nv_bfloat16 g_wk[CHN*CHN];
__device__ __nv_bfloat16 g_wv[CHN*CHN];
__device__ __nv_bfloat16 g_wp[CHN*CHN];

// ---------------- helpers ------------------------------------------------------
__device__ __forceinline__ uint32_t smem_u32(const void* p) {
    uint32_t a;
    asm("{ .reg .u64 t; cvta.to.shared.u64 t, %1; cvt.u32.u64 %0, t; }" : "=r"(a) : "l"(p));
    return a;
}
__device__ __forceinline__ void cpa16(uint32_t s, const void* g) {
    asm volatile("cp.async.cg.shared.global [%0], [%1], 16;" :: "r"(s), "l"(g) : "memory");
}
#define CPA_COMMIT() asm volatile("cp.async.commit_group;" ::: "memory")
#define CPA_WAIT2()  asm volatile("cp.async.wait_group 2;" ::: "memory")
#define CPA_WAIT0()  asm volatile("cp.async.wait_group 0;" ::: "memory")

__device__ __forceinline__ void ldsm4(uint32_t addr, uint32_t& r0, uint32_t& r1,
                                      uint32_t& r2, uint32_t& r3) {
    asm volatile("ldmatrix.sync.aligned.m8n8.x4.shared.b16 {%0,%1,%2,%3}, [%4];"
                 : "=r"(r0), "=r"(r1), "=r"(r2), "=r"(r3) : "r"(addr));
}

// ---------------- unified bf16 mma.sync GEMM ----------------------------------
// C[m][n] = scale * (sum_k A[m][k]*B[n][k]) + bias_m[m] + bias_n[n] (+resid, fp32)
// BM=128, BN=128, BK=64; 4 warps as 2(M) x 2(N); warp tile 64x64; 128 threads.
// 96 KB smem, ~240 regs -> 2 CTAs/SM.
#define BM 128
#define BN 128
#define BK 64
#define NSTAGE 3
#define ABYTES (BM*128)            // 16 KB
#define BBYTES (BN*128)            // 16 KB
#define STAGE_BYTES (ABYTES + BBYTES)
#define SMEM_TOTAL (NSTAGE*STAGE_BYTES)   // 96 KB

__global__ void __launch_bounds__(128, 2)
gemm_tc(const __nv_bfloat16* __restrict__ A, size_t strideA,
        const __nv_bfloat16* __restrict__ B, size_t strideB,
        void* __restrict__ Cv, size_t strideC, int ldC,
        const float* __restrict__ bias_m,
        const float* __restrict__ bias_n,
        const float* __restrict__ resid,
        float scale, int K, int out32) {
    extern __shared__ char smem[];
    uint32_t sb = smem_u32(smem);

    int tid  = threadIdx.x;
    int wid  = tid >> 5, lane = tid & 31;
    int wm = wid >> 1;         // 2 warps on M: 64 rows each
    int wn = wid & 1;          // 2 warps on N: 64 cols each
    int m0 = blockIdx.y * BM;
    int n0 = blockIdx.x * BN;
    const __nv_bfloat16* Ab = A + (size_t)blockIdx.z*strideA + (size_t)m0*K;
    const __nv_bfloat16* Bb = B + (size_t)blockIdx.z*strideB + (size_t)n0*K;

    float acc[4][8][4];
    #pragma unroll
    for (int i = 0; i < 4; i++)
        #pragma unroll
        for (int j = 0; j < 8; j++)
            #pragma unroll
            for (int r = 0; r < 4; r++) acc[i][j][r] = 0.f;

    // ---- tile copy: A 1024 + B 1024 16B-chunks; 8 + 8 per thread ----
    auto copy_stage = [&](int s, int k0) {
        uint32_t ab  = sb + s*STAGE_BYTES;
        uint32_t bbs = ab + ABYTES;
        #pragma unroll
        for (int i = 0; i < 8; i++) {
            int q = i*128 + tid;
            int r = q >> 3, c = q & 7;
            uint32_t off = r*128 + ((c ^ (r & 7)) << 4);
            cpa16(ab  + off, Ab + (size_t)r*K + k0 + c*8);
            cpa16(bbs + off, Bb + (size_t)r*K + k0 + c*8);
        }
        CPA_COMMIT();
    };

    int nt = K / BK;
    copy_stage(0, 0);
    copy_stage(1, BK);

    // ldmatrix address components
    int arow = wm*64 + (lane & 15);                     // + am*16
    int akc  = lane >> 4;                               // 0/1 -> +8 k elems
    int brow = wn*64 + (lane & 7) + ((lane >> 4) << 3); // + bt*16
    int bkc  = (lane >> 3) & 1;

    for (int it = 0; it < nt; it++) {
        if (it + 2 < nt) copy_stage((it + 2) % NSTAGE, (it + 2)*BK);
        if (it + 2 < nt) { CPA_WAIT2(); } else { CPA_WAIT0(); }
        __syncthreads();

        uint32_t as = sb + (it % NSTAGE)*STAGE_BYTES;
        uint32_t bs = as + ABYTES;

        #pragma unroll
        for (int ks = 0; ks < 4; ks++) {          // 4 x k16
            int kc = ks*2;
            uint32_t af[4][4];
            #pragma unroll
            for (int am = 0; am < 4; am++) {
                int r = arow + am*16;
                uint32_t addr = as + r*128 + (((kc + akc) ^ (r & 7)) << 4);
                ldsm4(addr, af[am][0], af[am][1], af[am][2], af[am][3]);
            }
            uint32_t bf[8][2];
            #pragma unroll
            for (int bt = 0; bt < 4; bt++) {
                int r = brow + bt*16;
                uint32_t addr = bs + r*128 + (((kc + bkc) ^ (r & 7)) << 4);
                ldsm4(addr, bf[bt*2][0], bf[bt*2][1], bf[bt*2+1][0], bf[bt*2+1][1]);
            }
            #pragma unroll
            for (int am = 0; am < 4; am++)
                #pragma unroll
                for (int an = 0; an < 8; an++) {
                    float* c = acc[am][an];
                    asm volatile(
                        "mma.sync.aligned.m16n8k16.row.col.f32.bf16.bf16.f32 "
                        "{%0,%1,%2,%3}, {%4,%5,%6,%7}, {%8,%9}, {%0,%1,%2,%3};"
                        : "+f"(c[0]), "+f"(c[1]), "+f"(c[2]), "+f"(c[3])
                        : "r"(af[am][0]), "r"(af[am][1]), "r"(af[am][2]), "r"(af[am][3]),
                          "r"(bf[an][0]), "r"(bf[an][1]));
                }
        }
        __syncthreads();
    }

    // ---- epilogue: all row-major, coalesced ----
    int g = lane >> 2, t = lane & 3;
    #pragma unroll
    for (int am = 0; am < 4; am++) {
        int ml = m0 + wm*64 + am*16 + g;
        int mh = ml + 8;
        float bml = bias_m ? bias_m[ml] : 0.f;
        float bmh = bias_m ? bias_m[mh] : 0.f;
        size_t rl = (size_t)blockIdx.z*strideC + (size_t)ml*ldC;
        size_t rh = (size_t)blockIdx.z*strideC + (size_t)mh*ldC;
        #pragma unroll
        for (int an = 0; an < 8; an++) {
            int ne = n0 + wn*64 + an*8 + 2*t;
            float v0 = acc[am][an][0]*scale + bml;
            float v1 = acc[am][an][1]*scale + bml;
            float v2 = acc[am][an][2]*scale + bmh;
            float v3 = acc[am][an][3]*scale + bmh;
            if (bias_n) {
                float b0 = __ldg(bias_n + ne), b1 = __ldg(bias_n + ne + 1);
                v0 += b0; v1 += b1; v2 += b0; v3 += b1;
            }
            if (!out32) {
                __nv_bfloat16* C = (__nv_bfloat16*)Cv;
                *reinterpret_cast<__nv_bfloat162*>(C + rl + ne) =
                    __nv_bfloat162{__float2bfloat16(v0), __float2bfloat16(v1)};
                *reinterpret_cast<__nv_bfloat162*>(C + rh + ne) =
                    __nv_bfloat162{__float2bfloat16(v2), __float2bfloat16(v3)};
            } else {
                float* C = (float*)Cv;
                float2 r0 = *reinterpret_cast<const float2*>(resid + rl + ne);
                float2 r1 = *reinterpret_cast<const float2*>(resid + rh + ne);
                *reinterpret_cast<float2*>(C + rl + ne) = float2{v0 + r0.x, v1 + r0.y};
                *reinterpret_cast<float2*>(C + rh + ne) = float2{v2 + r1.x, v3 + r1.y};
            }
        }
    }
}

// ---------------- fp32 -> bf16 weight convert (all 4 weights, 1 launch) -------
#define WN (CHN*CHN)
__global__ void cvt4_kernel(const float* __restrict__ s0, const float* __restrict__ s1,
                            const float* __restrict__ s2, const float* __restrict__ s3,
                            __nv_bfloat16* __restrict__ d0, __nv_bfloat16* __restrict__ d1,
                            __nv_bfloat16* __restrict__ d2, __nv_bfloat16* __restrict__ d3) {
    int i = blockIdx.x * blockDim.x + threadIdx.x;
    int sel = i >> 18;            // WN = 2^18
    int off = i & (WN - 1);
    const float* s = sel == 0 ? s0 : sel == 1 ? s1 : sel == 2 ? s2 : s3;
    __nv_bfloat16* d = sel == 0 ? d0 : sel == 1 ? d1 : sel == 2 ? d2 : d3;
    d[off] = __float2bfloat16(s[off]);
}

// ---------------- GroupNorm -> h^T bf16 [b][i][c] -----------------------------
__global__ void gn_kernel(const float* __restrict__ x,
                          const float* __restrict__ w,
                          const float* __restrict__ b,
                          __nv_bfloat16* __restrict__ ht) {
    int batch = blockIdx.x >> 5;
    int grp   = blockIdx.x & 31;
    const float* xp = x + ((size_t)batch*CHN + (size_t)grp*CPG) * NPIX;
    const int GE = CPG * NPIX;
    int tid = threadIdx.x;

    float s = 0.f, ss = 0.f;
    for (int i = tid; i < GE; i += 256) {
        float v = xp[i];
        s += v; ss += v*v;
    }
    __shared__ float r1[256], r2[256];
    r1[tid] = s; r2[tid] = ss;
    __syncthreads();
    for (int st = 128; st > 0; st >>= 1) {
        if (tid < st) { r1[tid] += r1[tid+st]; r2[tid] += r2[tid+st]; }
        __syncthreads();
    }
    float mean = r1[0] / (float)GE;
    float var  = r2[0] / (float)GE - mean*mean;
    float rstd = rsqrtf(var + 1e-6f);

    float wl[CPG], bl[CPG];
    #pragma unroll
    for (int c = 0; c < CPG; c++) { wl[c] = w[grp*CPG+c]; bl[c] = b[grp*CPG+c]; }

    for (int n = tid; n < NPIX; n += 256) {
        union { __nv_bfloat16 v[CPG]; uint4 u[2]; } pk;
        #pragma unroll
        for (int c = 0; c < CPG; c++) {
            float xv = xp[(size_t)c*NPIX + n];
            pk.v[c] = __float2bfloat16((xv - mean) * rstd * wl[c] + bl[c]);
        }
        uint4* dst = reinterpret_cast<uint4*>(ht + ((size_t)batch*NPIX + n)*CHN + grp*CPG);
        dst[0] = pk.u[0]; dst[1] = pk.u[1];
    }
}

// ---------------- row softmax, bf16 in-place ----------------------------------
__global__ void softmax_kernel(__nv_bfloat16* __restrict__ attn) {
    __nv_bfloat16* p = attn + (size_t)blockIdx.x * NPIX;
    __shared__ float buf[NPIX];
    __shared__ float red[8];
    int tid = threadIdx.x, lane = tid & 31, wid = tid >> 5;

    float mx = -1e30f;
    for (int i = tid; i < NPIX/8; i += 256) {
        uint4 raw = reinterpret_cast<const uint4*>(p)[i];
        const __nv_bfloat162* h2 = reinterpret_cast<const __nv_bfloat162*>(&raw);
        #pragma unroll
        for (int j = 0; j < 4; j++) {
            float2 f = __bfloat1622float2(h2[j]);
            buf[i*8 + 2*j]   = f.x;
            buf[i*8 + 2*j+1] = f.y;
            mx = fmaxf(mx, fmaxf(f.x, f.y));
        }
    }
    #pragma unroll
    for (int o = 16; o > 0; o >>= 1) mx = fmaxf(mx, __shfl_xor_sync(0xffffffffu, mx, o));
    if (lane == 0) red[wid] = mx;
    __syncthreads();
    if (tid == 0) {
        float m = red[0];
        #pragma unroll
        for (int i = 1; i < 8; i++) m = fmaxf(m, red[i]);
        red[0] = m;
    }
    __syncthreads();
    mx = red[0];
    __syncthreads();

    float s = 0.f;
    for (int i = tid; i < NPIX; i += 256) {
        float e = __expf(buf[i] - mx);
        buf[i] = e;
        s += e;
    }
    #pragma unroll
    for (int o = 16; o > 0; o >>= 1) s += __shfl_xor_sync(0xffffffffu, s, o);
    if (lane == 0) red[wid] = s;
    __syncthreads();
    if (tid == 0) {
        float m = 0.f;
        #pragma unroll
        for (int i = 0; i < 8; i++) m += red[i];
        red[0] = m;
    }
    __syncthreads();
    float inv = 1.0f / red[0];

    for (int i = tid; i < NPIX/8; i += 256) {
        uint4 raw;
        __nv_bfloat162* h2 = reinterpret_cast<__nv_bfloat162*>(&raw);
        #pragma unroll
        for (int j = 0; j < 4; j++) {
            h2[j] = __nv_bfloat162{__float2bfloat16(buf[i*8+2*j]   * inv),
                                   __float2bfloat16(buf[i*8+2*j+1] * inv)};
        }
        reinterpret_cast<uint4*>(p)[i] = raw;
    }
}

// ---------------- launch -------------------------------------------------------
extern "C" void kernel_launch(void* const* d_in, const int* in_sizes, int n_in,
                              void* d_out, int out_size) {
    const float* x    = (const float*)d_in[0];
    const float* gn_w = (const float*)d_in[1];
    const float* gn_b = (const float*)d_in[2];
    const float* q_w  = (const float*)d_in[3];
    const float* q_b  = (const float*)d_in[4];
    const float* k_w  = (const float*)d_in[5];
    const float* k_b  = (const float*)d_in[6];
    const float* v_w  = (const float*)d_in[7];
    const float* v_b  = (const float*)d_in[8];
    const float* p_w  = (const float*)d_in[9];
    const float* p_b  = (const float*)d_in[10];
    float* out = (float*)d_out;

    __nv_bfloat16 *ht, *qt, *kt, *v, *ot, *attn, *wq, *wk, *wv, *wp;
    cudaGetSymbolAddress((void**)&ht, g_ht);
    cudaGetSymbolAddress((void**)&qt, g_qt);
    cudaGetSymbolAddress((void**)&kt, g_kt);
    cudaGetSymbolAddress((void**)&v,  g_v);
    cudaGetSymbolAddress((void**)&ot, g_ot);
    cudaGetSymbolAddress((void**)&attn, g_attn);
    cudaGetSymbolAddress((void**)&wq, g_wq);
    cudaGetSymbolAddress((void**)&wk, g_wk);
    cudaGetSymbolAddress((void**)&wv, g_wv);
    cudaGetSymbolAddress((void**)&wp, g_wp);

    cudaFuncSetAttribute(gemm_tc, cudaFuncAttributeMaxDynamicSharedMemorySize, SMEM_TOTAL);

    cvt4_kernel<<<4*WN/256, 256>>>(q_w, k_w, v_w, p_w, wq, wk, wv, wp);
    gn_kernel<<<BATCH*GROUPS, 256>>>(x, gn_w, gn_b, ht);

    size_t sHT = (size_t)NPIX*CHN;
    size_t sCN = (size_t)CHN*NPIX;
    size_t sNN = (size_t)NPIX*NPIX;

    // q^T[i][c] = sum_k ht[i][k] Wq[c][k] + qb[c]  (M=NPIX, N=CHN, K=CHN)
    dim3 qkgrid(CHN/BN, NPIX/BM, BATCH);
    gemm_tc<<<qkgrid, 128, SMEM_TOTAL>>>(ht, sHT, wq, 0, qt, sHT, CHN,
                                         nullptr, q_b, nullptr, 1.f, CHN, 0);
    gemm_tc<<<qkgrid, 128, SMEM_TOTAL>>>(ht, sHT, wk, 0, kt, sHT, CHN,
                                         nullptr, k_b, nullptr, 1.f, CHN, 0);
    // v[c][j] = sum_k Wv[c][k] ht[j][k] + vb[c]   (M=CHN, N=NPIX, K=CHN)
    dim3 vgrid(NPIX/BN, CHN/BM, BATCH);
    gemm_tc<<<vgrid, 128, SMEM_TOTAL>>>(wv, 0, ht, sHT, v, sCN, NPIX,
                                        v_b, nullptr, nullptr, 1.f, CHN, 0);
    // attn[i][j] = scale * sum_c q^T[i][c] k^T[j][c]  (M=N=NPIX, K=CHN)
    dim3 lgrid(NPIX/BN, NPIX/BM, BATCH);
    gemm_tc<<<lgrid, 128, SMEM_TOTAL>>>(qt, sHT, kt, sHT, attn, sNN, NPIX,
                                        nullptr, nullptr, nullptr,
                                        0.044194173824159216f, CHN, 0);

    softmax_kernel<<<BATCH*NPIX, 256>>>(attn);

    // o^T[i][c] = sum_j attn[i][j] v[c][j]  (M=NPIX, N=CHN, K=NPIX)
    dim3 ogrid(CHN/BN, NPIX/BM, BATCH);
    gemm_tc<<<ogrid, 128, SMEM_TOTAL>>>(attn, sNN, v, sCN, ot, sHT, CHN,
                                        nullptr, nullptr, nullptr, 1.f, NPIX, 0);

    // out[c][n] = sum_k Wp[c][k] o^T[n][k] + pb[c] + x  (fp32 + residual)
    dim3 pgrid(NPIX/BN, CHN/BM, BATCH);
    gemm_tc<<<pgrid, 128, SMEM_TOTAL>>>(wp, 0, ot, sHT, out, sCN, NPIX,
                                        p_b, nullptr, x, 1.f, CHN, 1);
}

// round 7
// speedup vs baseline: 1.1878x; 1.0162x over previous
#include <cuda_runtime.h>
#include <cuda_bf16.h>
#include <cstdint>
#include <math.h>

#define BATCH 8
#define CHN 512
#define NPIX 4096
#define GROUPS 32
#define CPG 16

// ---------------- scratch (__device__ globals) -------------------------------
__device__ __nv_bfloat16 g_ht[(size_t)BATCH*NPIX*CHN];     // h^T  [b][i][c]
__device__ __nv_bfloat16 g_qt[(size_t)BATCH*NPIX*CHN];     // q^T  [b][i][c]
__device__ __nv_bfloat16 g_kt[(size_t)BATCH*NPIX*CHN];     // k^T  [b][j][c]
__device__ __nv_bfloat16 g_v [(size_t)BATCH*CHN*NPIX];     // v    [b][c][j]
__device__ __nv_bfloat16 g_ot[(size_t)BATCH*NPIX*CHN];     // o^T  [b][i][c]
__device__ __nv_bfloat16 g_attn[(size_t)BATCH*NPIX*NPIX];  // attn [b][i][j]
__device__ __nv_bfloat16 g_wq[CHN*CHN];
__device__ __nv_bfloat16 g_wk[CHN*CHN];
__device__ __nv_bfloat16 g_wv[CHN*CHN];
__device__ __nv_bfloat16 g_wp[CHN*CHN];

// ---------------- helpers ------------------------------------------------------
__device__ __forceinline__ uint32_t smem_u32(const void* p) {
    uint32_t a;
    asm("{ .reg .u64 t; cvta.to.shared.u64 t, %1; cvt.u32.u64 %0, t; }" : "=r"(a) : "l"(p));
    return a;
}
__device__ __forceinline__ void cpa16(uint32_t s, const void* g) {
    asm volatile("cp.async.cg.shared.global [%0], [%1], 16;" :: "r"(s), "l"(g) : "memory");
}
#define CPA_COMMIT() asm volatile("cp.async.commit_group;" ::: "memory")
#define CPA_WAIT2()  asm volatile("cp.async.wait_group 2;" ::: "memory")
#define CPA_WAIT0()  asm volatile("cp.async.wait_group 0;" ::: "memory")

__device__ __forceinline__ void ldsm4(uint32_t addr, uint32_t& r0, uint32_t& r1,
                                      uint32_t& r2, uint32_t& r3) {
    asm volatile("ldmatrix.sync.aligned.m8n8.x4.shared.b16 {%0,%1,%2,%3}, [%4];"
                 : "=r"(r0), "=r"(r1), "=r"(r2), "=r"(r3) : "r"(addr));
}

// ---------------- unified bf16 mma.sync GEMM ----------------------------------
// C[m][n] = scale * (sum_k A[m][k]*B[n][k]) + bias_m[m] + bias_n[n] (+resid, fp32)
// BM=128, BN=128, BK=64; 4 warps as 2(M) x 2(N); warp tile 64x64; 128 threads.
// Register-level double buffering of ldmatrix fragments.
#define BM 128
#define BN 128
#define BK 64
#define NSTAGE 3
#define ABYTES (BM*128)
#define BBYTES (BN*128)
#define STAGE_BYTES (ABYTES + BBYTES)
#define SMEM_TOTAL (NSTAGE*STAGE_BYTES)   // 96 KB

__global__ void __launch_bounds__(128, 2)
gemm_tc(const __nv_bfloat16* __restrict__ A, size_t strideA,
        const __nv_bfloat16* __restrict__ B, size_t strideB,
        void* __restrict__ Cv, size_t strideC, int ldC,
        const float* __restrict__ bias_m,
        const float* __restrict__ bias_n,
        const float* __restrict__ resid,
        float scale, int K, int out32) {
    extern __shared__ char smem[];
    uint32_t sb = smem_u32(smem);

    int tid  = threadIdx.x;
    int wid  = tid >> 5, lane = tid & 31;
    int wm = wid >> 1;         // 2 warps on M: 64 rows each
    int wn = wid & 1;          // 2 warps on N: 64 cols each
    int m0 = blockIdx.y * BM;
    int n0 = blockIdx.x * BN;
    const __nv_bfloat16* Ab = A + (size_t)blockIdx.z*strideA + (size_t)m0*K;
    const __nv_bfloat16* Bb = B + (size_t)blockIdx.z*strideB + (size_t)n0*K;

    float acc[4][8][4];
    #pragma unroll
    for (int i = 0; i < 4; i++)
        #pragma unroll
        for (int j = 0; j < 8; j++)
            #pragma unroll
            for (int r = 0; r < 4; r++) acc[i][j][r] = 0.f;

    // ---- tile copy: A 1024 + B 1024 16B-chunks; 8 + 8 per thread ----
    auto copy_stage = [&](int s, int k0) {
        uint32_t ab  = sb + s*STAGE_BYTES;
        uint32_t bbs = ab + ABYTES;
        #pragma unroll
        for (int i = 0; i < 8; i++) {
            int q = i*128 + tid;
            int r = q >> 3, c = q & 7;
            uint32_t off = r*128 + ((c ^ (r & 7)) << 4);
            cpa16(ab  + off, Ab + (size_t)r*K + k0 + c*8);
            cpa16(bbs + off, Bb + (size_t)r*K + k0 + c*8);
        }
        CPA_COMMIT();
    };

    int nt = K / BK;
    copy_stage(0, 0);
    copy_stage(1, BK);

    // ---- precomputed ldmatrix address components ----
    int arow = wm*64 + (lane & 15);
    int akc  = lane >> 4;
    int brow = wn*64 + (lane & 7) + ((lane >> 4) << 3);
    int bkc  = (lane >> 3) & 1;
    int xra = arow & 7, xrb = brow & 7;     // constant across am/bt (steps of 16)

    uint32_t a_base[4], b_base[4], xa[4], xb[4];
    #pragma unroll
    for (int i = 0; i < 4; i++) {
        a_base[i] = (uint32_t)(arow + i*16) * 128;
        b_base[i] = (uint32_t)(brow + i*16) * 128;
        xa[i] = (uint32_t)(((i*2 + akc) ^ xra) << 4);
        xb[i] = (uint32_t)(((i*2 + bkc) ^ xrb) << 4);
    }

    uint32_t af[2][4][4], bf[2][8][2];

    for (int it = 0; it < nt; it++) {
        if (it + 2 < nt) copy_stage((it + 2) % NSTAGE, (it + 2)*BK);
        if (it + 2 < nt) { CPA_WAIT2(); } else { CPA_WAIT0(); }
        __syncthreads();

        uint32_t as = sb + (it % NSTAGE)*STAGE_BYTES;
        uint32_t bs = as + ABYTES;

        // preload ks=0 fragments into buffer 0
        #pragma unroll
        for (int am = 0; am < 4; am++)
            ldsm4(as + a_base[am] + xa[0], af[0][am][0], af[0][am][1], af[0][am][2], af[0][am][3]);
        #pragma unroll
        for (int bt = 0; bt < 4; bt++)
            ldsm4(bs + b_base[bt] + xb[0], bf[0][bt*2][0], bf[0][bt*2][1],
                                           bf[0][bt*2+1][0], bf[0][bt*2+1][1]);

        #pragma unroll
        for (int ks = 0; ks < 4; ks++) {
            int cur = ks & 1;
            if (ks < 3) {                     // prefetch ks+1 into other buffer
                int nxt = cur ^ 1;
                #pragma unroll
                for (int am = 0; am < 4; am++)
                    ldsm4(as + a_base[am] + xa[ks+1],
                          af[nxt][am][0], af[nxt][am][1], af[nxt][am][2], af[nxt][am][3]);
                #pragma unroll
                for (int bt = 0; bt < 4; bt++)
                    ldsm4(bs + b_base[bt] + xb[ks+1],
                          bf[nxt][bt*2][0], bf[nxt][bt*2][1],
                          bf[nxt][bt*2+1][0], bf[nxt][bt*2+1][1]);
            }
            #pragma unroll
            for (int am = 0; am < 4; am++)
                #pragma unroll
                for (int an = 0; an < 8; an++) {
                    float* c = acc[am][an];
                    asm volatile(
                        "mma.sync.aligned.m16n8k16.row.col.f32.bf16.bf16.f32 "
                        "{%0,%1,%2,%3}, {%4,%5,%6,%7}, {%8,%9}, {%0,%1,%2,%3};"
                        : "+f"(c[0]), "+f"(c[1]), "+f"(c[2]), "+f"(c[3])
                        : "r"(af[cur][am][0]), "r"(af[cur][am][1]),
                          "r"(af[cur][am][2]), "r"(af[cur][am][3]),
                          "r"(bf[cur][an][0]), "r"(bf[cur][an][1]));
                }
        }
        __syncthreads();
    }

    // ---- epilogue: all row-major, coalesced ----
    int g = lane >> 2, t = lane & 3;
    #pragma unroll
    for (int am = 0; am < 4; am++) {
        int ml = m0 + wm*64 + am*16 + g;
        int mh = ml + 8;
        float bml = bias_m ? bias_m[ml] : 0.f;
        float bmh = bias_m ? bias_m[mh] : 0.f;
        size_t rl = (size_t)blockIdx.z*strideC + (size_t)ml*ldC;
        size_t rh = (size_t)blockIdx.z*strideC + (size_t)mh*ldC;
        #pragma unroll
        for (int an = 0; an < 8; an++) {
            int ne = n0 + wn*64 + an*8 + 2*t;
            float v0 = acc[am][an][0]*scale + bml;
            float v1 = acc[am][an][1]*scale + bml;
            float v2 = acc[am][an][2]*scale + bmh;
            float v3 = acc[am][an][3]*scale + bmh;
            if (bias_n) {
                float b0 = __ldg(bias_n + ne), b1 = __ldg(bias_n + ne + 1);
                v0 += b0; v1 += b1; v2 += b0; v3 += b1;
            }
            if (!out32) {
                __nv_bfloat16* C = (__nv_bfloat16*)Cv;
                *reinterpret_cast<__nv_bfloat162*>(C + rl + ne) =
                    __nv_bfloat162{__float2bfloat16(v0), __float2bfloat16(v1)};
                *reinterpret_cast<__nv_bfloat162*>(C + rh + ne) =
                    __nv_bfloat162{__float2bfloat16(v2), __float2bfloat16(v3)};
            } else {
                float* C = (float*)Cv;
                float2 r0 = *reinterpret_cast<const float2*>(resid + rl + ne);
                float2 r1 = *reinterpret_cast<const float2*>(resid + rh + ne);
                *reinterpret_cast<float2*>(C + rl + ne) = float2{v0 + r0.x, v1 + r0.y};
                *reinterpret_cast<float2*>(C + rh + ne) = float2{v2 + r1.x, v3 + r1.y};
            }
        }
    }
}

// ---------------- fp32 -> bf16 weight convert (all 4 weights, 1 launch) -------
#define WN (CHN*CHN)
__global__ void cvt4_kernel(const float* __restrict__ s0, const float* __restrict__ s1,
                            const float* __restrict__ s2, const float* __restrict__ s3,
                            __nv_bfloat16* __restrict__ d0, __nv_bfloat16* __restrict__ d1,
                            __nv_bfloat16* __restrict__ d2, __nv_bfloat16* __restrict__ d3) {
    int i = blockIdx.x * blockDim.x + threadIdx.x;
    int sel = i >> 18;
    int off = i & (WN - 1);
    const float* s = sel == 0 ? s0 : sel == 1 ? s1 : sel == 2 ? s2 : s3;
    __nv_bfloat16* d = sel == 0 ? d0 : sel == 1 ? d1 : sel == 2 ? d2 : d3;
    d[off] = __float2bfloat16(s[off]);
}

// ---------------- GroupNorm -> h^T bf16 [b][i][c] -----------------------------
__global__ void gn_kernel(const float* __restrict__ x,
                          const float* __restrict__ w,
                          const float* __restrict__ b,
                          __nv_bfloat16* __restrict__ ht) {
    int batch = blockIdx.x >> 5;
    int grp   = blockIdx.x & 31;
    const float* xp = x + ((size_t)batch*CHN + (size_t)grp*CPG) * NPIX;
    const int GE = CPG * NPIX;
    int tid = threadIdx.x;

    float s = 0.f, ss = 0.f;
    for (int i = tid; i < GE; i += 256) {
        float v = xp[i];
        s += v; ss += v*v;
    }
    __shared__ float r1[256], r2[256];
    r1[tid] = s; r2[tid] = ss;
    __syncthreads();
    for (int st = 128; st > 0; st >>= 1) {
        if (tid < st) { r1[tid] += r1[tid+st]; r2[tid] += r2[tid+st]; }
        __syncthreads();
    }
    float mean = r1[0] / (float)GE;
    float var  = r2[0] / (float)GE - mean*mean;
    float rstd = rsqrtf(var + 1e-6f);

    float wl[CPG], bl[CPG];
    #pragma unroll
    for (int c = 0; c < CPG; c++) { wl[c] = w[grp*CPG+c]; bl[c] = b[grp*CPG+c]; }

    for (int n = tid; n < NPIX; n += 256) {
        union { __nv_bfloat16 v[CPG]; uint4 u[2]; } pk;
        #pragma unroll
        for (int c = 0; c < CPG; c++) {
            float xv = xp[(size_t)c*NPIX + n];
            pk.v[c] = __float2bfloat16((xv - mean) * rstd * wl[c] + bl[c]);
        }
        uint4* dst = reinterpret_cast<uint4*>(ht + ((size_t)batch*NPIX + n)*CHN + grp*CPG);
        dst[0] = pk.u[0]; dst[1] = pk.u[1];
    }
}

// ---------------- row softmax, bf16 in-place ----------------------------------
__global__ void softmax_kernel(__nv_bfloat16* __restrict__ attn) {
    __nv_bfloat16* p = attn + (size_t)blockIdx.x * NPIX;
    __shared__ float buf[NPIX];
    __shared__ float red[8];
    int tid = threadIdx.x, lane = tid & 31, wid = tid >> 5;

    float mx = -1e30f;
    for (int i = tid; i < NPIX/8; i += 256) {
        uint4 raw = reinterpret_cast<const uint4*>(p)[i];
        const __nv_bfloat162* h2 = reinterpret_cast<const __nv_bfloat162*>(&raw);
        #pragma unroll
        for (int j = 0; j < 4; j++) {
            float2 f = __bfloat1622float2(h2[j]);
            buf[i*8 + 2*j]   = f.x;
            buf[i*8 + 2*j+1] = f.y;
            mx = fmaxf(mx, fmaxf(f.x, f.y));
        }
    }
    #pragma unroll
    for (int o = 16; o > 0; o >>= 1) mx = fmaxf(mx, __shfl_xor_sync(0xffffffffu, mx, o));
    if (lane == 0) red[wid] = mx;
    __syncthreads();
    if (tid == 0) {
        float m = red[0];
        #pragma unroll
        for (int i = 1; i < 8; i++) m = fmaxf(m, red[i]);
        red[0] = m;
    }
    __syncthreads();
    mx = red[0];
    __syncthreads();

    float s = 0.f;
    for (int i = tid; i < NPIX; i += 256) {
        float e = __expf(buf[i] - mx);
        buf[i] = e;
        s += e;
    }
    #pragma unroll
    for (int o = 16; o > 0; o >>= 1) s += __shfl_xor_sync(0xffffffffu, s, o);
    if (lane == 0) red[wid] = s;
    __syncthreads();
    if (tid == 0) {
        float m = 0.f;
        #pragma unroll
        for (int i = 0; i < 8; i++) m += red[i];
        red[0] = m;
    }
    __syncthreads();
    float inv = 1.0f / red[0];

    for (int i = tid; i < NPIX/8; i += 256) {
        uint4 raw;
        __nv_bfloat162* h2 = reinterpret_cast<__nv_bfloat162*>(&raw);
        #pragma unroll
        for (int j = 0; j < 4; j++) {
            h2[j] = __nv_bfloat162{__float2bfloat16(buf[i*8+2*j]   * inv),
                                   __float2bfloat16(buf[i*8+2*j+1] * inv)};
        }
        reinterpret_cast<uint4*>(p)[i] = raw;
    }
}

// ---------------- launch -------------------------------------------------------
extern "C" void kernel_launch(void* const* d_in, const int* in_sizes, int n_in,
                              void* d_out, int out_size) {
    const float* x    = (const float*)d_in[0];
    const float* gn_w = (const float*)d_in[1];
    const float* gn_b = (const float*)d_in[2];
    const float* q_w  = (const float*)d_in[3];
    const float* q_b  = (const float*)d_in[4];
    const float* k_w  = (const float*)d_in[5];
    const float* k_b  = (const float*)d_in[6];
    const float* v_w  = (const float*)d_in[7];
    const float* v_b  = (const float*)d_in[8];
    const float* p_w  = (const float*)d_in[9];
    const float* p_b  = (const float*)d_in[10];
    float* out = (float*)d_out;

    __nv_bfloat16 *ht, *qt, *kt, *v, *ot, *attn, *wq, *wk, *wv, *wp;
    cudaGetSymbolAddress((void**)&ht, g_ht);
    cudaGetSymbolAddress((void**)&qt, g_qt);
    cudaGetSymbolAddress((void**)&kt, g_kt);
    cudaGetSymbolAddress((void**)&v,  g_v);
    cudaGetSymbolAddress((void**)&ot, g_ot);
    cudaGetSymbolAddress((void**)&attn, g_attn);
    cudaGetSymbolAddress((void**)&wq, g_wq);
    cudaGetSymbolAddress((void**)&wk, g_wk);
    cudaGetSymbolAddress((void**)&wv, g_wv);
    cudaGetSymbolAddress((void**)&wp, g_wp);

    cudaFuncSetAttribute(gemm_tc, cudaFuncAttributeMaxDynamicSharedMemorySize, SMEM_TOTAL);

    cvt4_kernel<<<4*WN/256, 256>>>(q_w, k_w, v_w, p_w, wq, wk, wv, wp);
    gn_kernel<<<BATCH*GROUPS, 256>>>(x, gn_w, gn_b, ht);

    size_t sHT = (size_t)NPIX*CHN;
    size_t sCN = (size_t)CHN*NPIX;
    size_t sNN = (size_t)NPIX*NPIX;

    dim3 qkgrid(CHN/BN, NPIX/BM, BATCH);
    gemm_tc<<<qkgrid, 128, SMEM_TOTAL>>>(ht, sHT, wq, 0, qt, sHT, CHN,
                                         nullptr, q_b, nullptr, 1.f, CHN, 0);
    gemm_tc<<<qkgrid, 128, SMEM_TOTAL>>>(ht, sHT, wk, 0, kt, sHT, CHN,
                                         nullptr, k_b, nullptr, 1.f, CHN, 0);
    dim3 vgrid(NPIX/BN, CHN/BM, BATCH);
    gemm_tc<<<vgrid, 128, SMEM_TOTAL>>>(wv, 0, ht, sHT, v, sCN, NPIX,
                                        v_b, nullptr, nullptr, 1.f, CHN, 0);
    dim3 lgrid(NPIX/BN, NPIX/BM, BATCH);
    gemm_tc<<<lgrid, 128, SMEM_TOTAL>>>(qt, sHT, kt, sHT, attn, sNN, NPIX,
                                        nullptr, nullptr, nullptr,
                                        0.044194173824159216f, CHN, 0);

    softmax_kernel<<<BATCH*NPIX, 256>>>(attn);

    dim3 ogrid(CHN/BN, NPIX/BM, BATCH);
    gemm_tc<<<ogrid, 128, SMEM_TOTAL>>>(attn, sNN, v, sCN, ot, sHT, CHN,
                                        nullptr, nullptr, nullptr, 1.f, NPIX, 0);

    dim3 pgrid(NPIX/BN, CHN/BM, BATCH);
    gemm_tc<<<pgrid, 128, SMEM_TOTAL>>>(wp, 0, ot, sHT, out, sCN, NPIX,
                                        p_b, nullptr, x, 1.f, CHN, 1);
}